// round 15
// baseline (speedup 1.0000x reference)
#include <cuda_runtime.h>
#include <cstdint>
#include <cstddef>

// Problem constants
#define NB    8
#define SS    1024
#define DIN   1280
#define RNK   64
#define DOUT  1280
#define MTOT  (NB * SS)                  // 8192
#define DOWN_SIZE (RNK * DIN)            // 81920
#define UP_SIZE   (DOUT * RNK)           // 81920
#define EMB_STRIDE (DOWN_SIZE + UP_SIZE) // 163840

#define NSPLIT 8                         // K split for GEMM1 (chunks of 160)

#define M16   (MTOT / 16)                // 512 m16-blocks
#define HQ_N  (M16 * 8 * 32)             // 131072 uint4 slots (h fragments)
#define WDP_N (NB * 80 * 8 * 32)         // 163840 uint4 (W_down fragments)
#define WUP_N (NB * 160 * 4 * 32)        // 163840 uint4 (W_up fragments)

// Device scratch (static — no allocation)
__device__ float4 g_hp4[NSPLIT * HQ_N];  // split-K partials, fragment order, fp32
__device__ uint4  g_hq[HQ_N];            // reduced h, tf32, A-fragment packed
__device__ uint4  g_wdp[WDP_N];          // W_down, tf32, B-fragment packed
__device__ uint4  g_wup[WUP_N];          // W_up,   tf32, B-fragment packed

__device__ __forceinline__ unsigned f2tf(float f) {
    unsigned u;
    asm("cvt.rna.tf32.f32 %0, %1;" : "=r"(u) : "f"(f));
    return u;
}

__device__ __forceinline__ uint4 f4totf(float4 v) {
    uint4 u;
    u.x = f2tf(v.x); u.y = f2tf(v.y); u.z = f2tf(v.z); u.w = f2tf(v.w);
    return u;
}

__device__ __forceinline__ void mma_tf32(float c[4],
                                         unsigned a0, unsigned a1, unsigned a2, unsigned a3,
                                         unsigned b0, unsigned b1) {
    asm volatile(
        "mma.sync.aligned.m16n8k8.row.col.f32.tf32.tf32.f32 "
        "{%0,%1,%2,%3}, {%4,%5,%6,%7}, {%8,%9}, {%0,%1,%2,%3};"
        : "+f"(c[0]), "+f"(c[1]), "+f"(c[2]), "+f"(c[3])
        : "r"(a0), "r"(a1), "r"(a2), "r"(a3), "r"(b0), "r"(b1));
}

// ---------------------------------------------------------------------------
// Prepack: embed -> tf32 fragment-packed W_down / W_up.
//   B-fragment (m16n8k8, col-major B): lane(g,t) holds (k=t,n=g),(k=t+4,n=g);
//   two k8 steps packed per uint4: {b(k8e)0, b(k8e)1, b(k8o)0, b(k8o)1}.
//   g_wdp index: ((b*80 + k16)*8 + n8)*32 + lane      (k over d_in: 80 k16)
//   g_wup index: ((b*160 + n8)*4 + k16)*32 + lane     (k over rank: 4 k16)
// ---------------------------------------------------------------------------
__global__ __launch_bounds__(256) void lora_prepack(const float* __restrict__ embed) {
    int i = blockIdx.x * 256 + threadIdx.x;
    int lane = i & 31;
    int g = lane >> 2, t = lane & 3;
    if (i < WDP_N) {
        int r = i >> 5;
        int n8  = r & 7;  r >>= 3;
        int k16 = r % 80;
        int b   = r / 80;
        const float* W = embed + (size_t)b * EMB_STRIDE
                       + (size_t)(n8 * 8 + g) * DIN + k16 * 16;
        uint4 o;
        o.x = f2tf(W[t]); o.y = f2tf(W[t + 4]);
        o.z = f2tf(W[8 + t]); o.w = f2tf(W[12 + t]);
        g_wdp[i] = o;
    } else {
        int j = i - WDP_N;
        int r = j >> 5;
        int k16 = r & 3;  r >>= 2;
        int n8  = r % 160;
        int b   = r / 160;
        const float* W = embed + (size_t)b * EMB_STRIDE + DOWN_SIZE
                       + (size_t)(n8 * 8 + g) * RNK + k16 * 16;
        uint4 o;
        o.x = f2tf(W[t]); o.y = f2tf(W[t + 4]);
        o.z = f2tf(W[8 + t]); o.w = f2tf(W[12 + t]);
        g_wup[j] = o;
    }
}

// ---------------------------------------------------------------------------
// GEMM1 (split-K=8): partial h[m,r] over one K chunk of 160.
//   grid (128, 8), block 256 (8 warps as 2m x 4n, warp tile 32m x 16n).
//   Two-phase staging: 80-k chunk in 21.5 KB smem -> ~4 CTAs (32 warps)/SM.
//   B (W_down): fragment LDG from g_wdp (L2-hot).
//   Epilogue: stage to smem, emit partials in A-fragment order (fp32).
// ---------------------------------------------------------------------------
#define G1S 84   // words per row: 80 + 4 pad (84 % 32 == 20 -> conflict-free)

__global__ __launch_bounds__(256) void lora_gemm1(const float* __restrict__ x) {
    __shared__ unsigned As[64 * G1S];   // 21504 B

    const int tid   = threadIdx.x;
    const int m0    = blockIdx.x * 64;
    const int split = blockIdx.y;
    const int batch = blockIdx.x >> 4;

    // staging map: thread = (row lr, quarter q); covers float4 at col c*16+q*4
    const int lr = tid & 63;
    const int q  = tid >> 6;           // 0..3
    const float* xrow = x + (size_t)(m0 + lr) * DIN + split * 160 + q * 4;

    const int wid  = tid >> 5;
    const int lane = tid & 31;
    const int wm = (wid & 1) * 32;     // 0 / 32
    const int wn = (wid >> 1) * 16;    // 0,16,32,48
    const int g = lane >> 2;
    const int t = lane & 3;

    const uint4* __restrict__ wb = g_wdp + (size_t)batch * (80 * 8 * 32);
    const int n8b = wn >> 3;           // 0,2,4,6

    float acc[2][2][4];
    #pragma unroll
    for (int mi = 0; mi < 2; mi++)
        #pragma unroll
        for (int ni = 0; ni < 2; ni++)
            #pragma unroll
            for (int j = 0; j < 4; j++) acc[mi][ni][j] = 0.f;

    #pragma unroll
    for (int p = 0; p < 2; p++) {
        if (p) __syncthreads();        // protect smem before restaging
        // ---- stage 80-k chunk: 5 LDG.128 per thread, tf32-converted ----
        #pragma unroll
        for (int c = 0; c < 5; c++) {
            float4 v = *reinterpret_cast<const float4*>(xrow + p * 80 + c * 16);
            *reinterpret_cast<uint4*>(&As[lr * G1S + c * 16 + q * 4]) = f4totf(v);
        }
        __syncthreads();

        #pragma unroll
        for (int c = 0; c < 5; c++) {
            const int k16g = split * 10 + p * 5 + c;   // global k16: 0..9 in order
            uint4 bu[2];
            #pragma unroll
            for (int ni = 0; ni < 2; ni++)
                bu[ni] = wb[((k16g * 8 + n8b + ni) << 5) + lane];

            #pragma unroll
            for (int hh = 0; hh < 2; hh++) {
                unsigned a[2][4];
                #pragma unroll
                for (int mi = 0; mi < 2; mi++) {
                    const unsigned* pp =
                        &As[(wm + mi * 16 + g) * G1S + c * 16 + hh * 8 + t];
                    a[mi][0] = pp[0];
                    a[mi][1] = pp[8 * G1S];
                    a[mi][2] = pp[4];
                    a[mi][3] = pp[8 * G1S + 4];
                }
                #pragma unroll
                for (int mi = 0; mi < 2; mi++)
                    #pragma unroll
                    for (int ni = 0; ni < 2; ni++) {
                        unsigned b0 = hh ? bu[ni].z : bu[ni].x;
                        unsigned b1 = hh ? bu[ni].w : bu[ni].y;
                        mma_tf32(acc[mi][ni], a[mi][0], a[mi][1], a[mi][2], a[mi][3], b0, b1);
                    }
            }
        }
    }

    // ---- epilogue: stage to smem, write partials in A-fragment order ----
    __syncthreads();
    float* s = reinterpret_cast<float*>(As);   // [64][68] floats (4352 <= 5376)
    #pragma unroll
    for (int mi = 0; mi < 2; mi++)
        #pragma unroll
        for (int ni = 0; ni < 2; ni++) {
            int row = wm + mi * 16 + g;
            int col = wn + ni * 8 + 2 * t;
            *reinterpret_cast<float2*>(&s[row * 68 + col]) =
                make_float2(acc[mi][ni][0], acc[mi][ni][1]);
            *reinterpret_cast<float2*>(&s[(row + 8) * 68 + col]) =
                make_float2(acc[mi][ni][2], acc[mi][ni][3]);
        }
    __syncthreads();

    float4* dst = g_hp4 + (size_t)split * HQ_N + (size_t)(m0 >> 4) * 256;
    #pragma unroll
    for (int jj = 0; jj < 4; jj++) {
        int idx = tid + jj * 256;              // 0..1023 = ml*256 + k8*32 + lane
        int ln  = idx & 31;
        int k8  = (idx >> 5) & 7;
        int ml  = idx >> 8;
        int gg = ln >> 2, tt = ln & 3;
        const float* r0 = &s[(ml * 16 + gg) * 68 + k8 * 8 + tt];
        const float* r1 = r0 + 8 * 68;
        dst[idx] = make_float4(r0[0], r1[0], r0[4], r1[4]);
    }
}

// ---------------------------------------------------------------------------
// Reduce: g_hq = cvt_tf32( sum over splits of g_hp4 ). Elementwise, coalesced.
// ---------------------------------------------------------------------------
__global__ __launch_bounds__(256) void lora_reduce() {
    int i = blockIdx.x * 256 + threadIdx.x;    // < HQ_N (grid 512)
    float4 sv = g_hp4[i];
    #pragma unroll
    for (int sp = 1; sp < NSPLIT; sp++) {
        float4 v = g_hp4[(size_t)sp * HQ_N + i];
        sv.x += v.x; sv.y += v.y; sv.z += v.z; sv.w += v.w;
    }
    uint4 o;
    o.x = f2tf(sv.x); o.y = f2tf(sv.y); o.z = f2tf(sv.z); o.w = f2tf(sv.w);
    g_hq[i] = o;
}

// ---------------------------------------------------------------------------
// GEMM2: out[m,o] = h[m,:] @ W_up[b]^T, K=64.
//   CTA 64m x 64n, block 128 (4 warps as 2m x 2n, warp tile 32m x 32n).
//   grid (128, 20) = 2560 CTAs. A/B fragments LDG from L2-hot packed scratch.
//   Staged-store epilogue: frags -> smem (stride 72, conflict-free) ->
//   coalesced STG.128 (2 lines per warp access vs 8 for direct STG.64).
// ---------------------------------------------------------------------------
__global__ __launch_bounds__(128) void lora_gemm2(float* __restrict__ out) {
    __shared__ float s[64 * 72];   // 18432 B

    const int tid   = threadIdx.x;
    const int m0    = blockIdx.x * 64;
    const int n0    = blockIdx.y * 64;
    const int batch = blockIdx.x >> 4;

    const int wid  = tid >> 5;
    const int lane = tid & 31;
    const int wm = (wid & 1) * 32;     // 0 / 32
    const int wn = (wid >> 1) * 32;    // 0 / 32
    const int g = lane >> 2;
    const int t = lane & 3;

    const uint4* __restrict__ Ab = g_hq + (size_t)((m0 + wm) >> 4) * 256 + lane;
    const uint4* __restrict__ Bb = g_wup
        + ((size_t)batch * 160 + ((n0 + wn) >> 3)) * 128 + lane;

    float acc[2][4][4];
    #pragma unroll
    for (int mi = 0; mi < 2; mi++)
        #pragma unroll
        for (int ni = 0; ni < 4; ni++)
            #pragma unroll
            for (int j = 0; j < 4; j++) acc[mi][ni][j] = 0.f;

    #pragma unroll
    for (int k16 = 0; k16 < 4; k16++) {
        uint4 alo[2], ahi[2], bu[4];
        #pragma unroll
        for (int mi = 0; mi < 2; mi++) {
            alo[mi] = Ab[mi * 256 + (2 * k16) * 32];
            ahi[mi] = Ab[mi * 256 + (2 * k16 + 1) * 32];
        }
        #pragma unroll
        for (int ni = 0; ni < 4; ni++)
            bu[ni] = Bb[ni * 128 + k16 * 32];

        #pragma unroll
        for (int mi = 0; mi < 2; mi++)
            #pragma unroll
            for (int ni = 0; ni < 4; ni++) {
                mma_tf32(acc[mi][ni], alo[mi].x, alo[mi].y, alo[mi].z, alo[mi].w,
                         bu[ni].x, bu[ni].y);
                mma_tf32(acc[mi][ni], ahi[mi].x, ahi[mi].y, ahi[mi].z, ahi[mi].w,
                         bu[ni].z, bu[ni].w);
            }
    }

    // ---- staged-store epilogue: stride-72 smem -> coalesced STG.128 ----
    #pragma unroll
    for (int mi = 0; mi < 2; mi++)
        #pragma unroll
        for (int ni = 0; ni < 4; ni++) {
            int row = wm + mi * 16 + g;
            int col = wn + ni * 8 + 2 * t;
            *reinterpret_cast<float2*>(&s[row * 72 + col]) =
                make_float2(acc[mi][ni][0], acc[mi][ni][1]);
            *reinterpret_cast<float2*>(&s[(row + 8) * 72 + col]) =
                make_float2(acc[mi][ni][2], acc[mi][ni][3]);
        }
    __syncthreads();

    #pragma unroll
    for (int j = 0; j < 8; j++) {
        int idx = tid + j * 128;               // 64 rows x 16 float4
        int row = idx >> 4;
        int seg = idx & 15;
        float4 v = *reinterpret_cast<const float4*>(&s[row * 72 + seg * 4]);
        *reinterpret_cast<float4*>(&out[(size_t)(m0 + row) * DOUT + n0 + seg * 4]) = v;
    }
}

// ---------------------------------------------------------------------------
extern "C" void kernel_launch(void* const* d_in, const int* in_sizes, int n_in,
                              void* d_out, int out_size) {
    const float* x     = (const float*)d_in[0];
    const float* embed = (const float*)d_in[1];
    if (n_in >= 2 && in_sizes[0] == NB * EMB_STRIDE) {
        x     = (const float*)d_in[1];
        embed = (const float*)d_in[0];
    }
    float* out = (float*)d_out;

    lora_prepack<<<(WDP_N + WUP_N) / 256, 256>>>(embed);
    lora_gemm1<<<dim3(128, NSPLIT), 256>>>(x);
    lora_reduce<<<HQ_N / 256, 256>>>();
    lora_gemm2<<<dim3(128, 20), 128>>>(out);
}

// round 16
// speedup vs baseline: 1.1325x; 1.1325x over previous
#include <cuda_runtime.h>
#include <cstdint>
#include <cstddef>

// Problem constants
#define NB    8
#define SS    1024
#define DIN   1280
#define RNK   64
#define DOUT  1280
#define MTOT  (NB * SS)                  // 8192
#define DOWN_SIZE (RNK * DIN)            // 81920
#define UP_SIZE   (DOUT * RNK)           // 81920
#define EMB_STRIDE (DOWN_SIZE + UP_SIZE) // 163840

#define NSPLIT 8                         // K split for GEMM1 (chunks of 160)

#define M16   (MTOT / 16)                // 512 m16-blocks
#define HQ_N  (M16 * 8 * 32)             // 131072 uint4 slots (h fragments)
#define WDP_N (NB * 80 * 8 * 32)         // 163840 uint4 (W_down fragments)
#define WUP_N (NB * 160 * 4 * 32)        // 163840 uint4 (W_up fragments)

// Device scratch (static — no allocation)
__device__ float4 g_hp4[NSPLIT * HQ_N];  // split-K partials, fragment order, fp32
__device__ uint4  g_hq[HQ_N];            // reduced h, tf32, A-fragment packed
__device__ uint4  g_wdp[WDP_N];          // W_down, tf32, B-fragment packed
__device__ uint4  g_wup[WUP_N];          // W_up,   tf32, B-fragment packed

__device__ __forceinline__ unsigned f2tf(float f) {
    unsigned u;
    asm("cvt.rna.tf32.f32 %0, %1;" : "=r"(u) : "f"(f));
    return u;
}

__device__ __forceinline__ uint4 f4totf(float4 v) {
    uint4 u;
    u.x = f2tf(v.x); u.y = f2tf(v.y); u.z = f2tf(v.z); u.w = f2tf(v.w);
    return u;
}

__device__ __forceinline__ void mma_tf32(float c[4],
                                         unsigned a0, unsigned a1, unsigned a2, unsigned a3,
                                         unsigned b0, unsigned b1) {
    asm volatile(
        "mma.sync.aligned.m16n8k8.row.col.f32.tf32.tf32.f32 "
        "{%0,%1,%2,%3}, {%4,%5,%6,%7}, {%8,%9}, {%0,%1,%2,%3};"
        : "+f"(c[0]), "+f"(c[1]), "+f"(c[2]), "+f"(c[3])
        : "r"(a0), "r"(a1), "r"(a2), "r"(a3), "r"(b0), "r"(b1));
}

// ---------------------------------------------------------------------------
// Prepack: embed -> tf32 fragment-packed W_down / W_up.
//   B-fragment (m16n8k8, col-major B): lane(g,t) holds (k=t,n=g),(k=t+4,n=g);
//   two k8 steps packed per uint4: {b(k8e)0, b(k8e)1, b(k8o)0, b(k8o)1}.
//   g_wdp index: ((b*80 + k16)*8 + n8)*32 + lane      (k over d_in: 80 k16)
//   g_wup index: ((b*160 + n8)*4 + k16)*32 + lane     (k over rank: 4 k16)
// ---------------------------------------------------------------------------
__global__ __launch_bounds__(256) void lora_prepack(const float* __restrict__ embed) {
    int i = blockIdx.x * 256 + threadIdx.x;
    int lane = i & 31;
    int g = lane >> 2, t = lane & 3;
    if (i < WDP_N) {
        int r = i >> 5;
        int n8  = r & 7;  r >>= 3;
        int k16 = r % 80;
        int b   = r / 80;
        const float* W = embed + (size_t)b * EMB_STRIDE
                       + (size_t)(n8 * 8 + g) * DIN + k16 * 16;
        uint4 o;
        o.x = f2tf(W[t]); o.y = f2tf(W[t + 4]);
        o.z = f2tf(W[8 + t]); o.w = f2tf(W[12 + t]);
        g_wdp[i] = o;
    } else {
        int j = i - WDP_N;
        int r = j >> 5;
        int k16 = r & 3;  r >>= 2;
        int n8  = r % 160;
        int b   = r / 160;
        const float* W = embed + (size_t)b * EMB_STRIDE + DOWN_SIZE
                       + (size_t)(n8 * 8 + g) * RNK + k16 * 16;
        uint4 o;
        o.x = f2tf(W[t]); o.y = f2tf(W[t + 4]);
        o.z = f2tf(W[8 + t]); o.w = f2tf(W[12 + t]);
        g_wup[j] = o;
    }
}

// ---------------------------------------------------------------------------
// GEMM1 (split-K=8): partial h[m,r] over one K chunk of 160.  [round-10 form]
//   grid (128, 8), block 128 (4 warps as 2m x 2n, warp tile 32m x 32n).
//   Single-stage smem: whole 64m x 160k x-chunk staged ONCE (20 LDG.128 per
//   thread, MLP=20), one syncthreads, then a barrier-free MMA stream.
//   B (W_down): fragment LDG from g_wdp (L2-hot).
//   Epilogue: stage to smem, emit partials in A-fragment order (fp32).
// ---------------------------------------------------------------------------
#define G1_STRIDE 164   // words per row: 160 + 4 pad (164 % 32 == 4 -> conflict-free)

__global__ __launch_bounds__(128) void lora_gemm1(const float* __restrict__ x) {
    __shared__ unsigned As[64 * G1_STRIDE];   // 41,984 B

    const int tid   = threadIdx.x;
    const int m0    = blockIdx.x * 64;
    const int split = blockIdx.y;
    const int batch = blockIdx.x >> 4;

    // ---- stage the full K-chunk: thread = (row lr, half lh) ----
    const int lr = tid >> 1;           // 0..63
    const int lh = tid & 1;            // 0..1
    {
        const float4* xg = reinterpret_cast<const float4*>(x)
                         + (size_t)(m0 + lr) * (DIN / 4) + split * 40 + lh * 4;
        #pragma unroll
        for (int kt = 0; kt < 5; kt++)
            #pragma unroll
            for (int j = 0; j < 4; j++)
                *reinterpret_cast<uint4*>(&As[lr * G1_STRIDE + kt * 32 + lh * 16 + j * 4]) =
                    f4totf(xg[kt * 8 + j]);
    }

    const int wid  = tid >> 5;
    const int lane = tid & 31;
    const int wm = (wid & 1) * 32;     // 0 / 32
    const int wn = (wid >> 1) * 32;    // 0 / 32
    const int g = lane >> 2;
    const int t = lane & 3;

    const uint4* __restrict__ wb = g_wdp + (size_t)batch * (80 * 8 * 32);
    const int n8b = wn >> 3;           // 0 or 4

    float acc[2][4][4];
    #pragma unroll
    for (int mi = 0; mi < 2; mi++)
        #pragma unroll
        for (int ni = 0; ni < 4; ni++)
            #pragma unroll
            for (int j = 0; j < 4; j++) acc[mi][ni][j] = 0.f;

    __syncthreads();   // the ONLY pre-mainloop barrier

    #pragma unroll
    for (int kt = 0; kt < 5; kt++) {
        // B fragments: global k16 = split*10 + kt*2 + j ; n8 = n8b..n8b+3
        uint4 bu[2][4];
        #pragma unroll
        for (int j = 0; j < 2; j++)
            #pragma unroll
            for (int ni = 0; ni < 4; ni++)
                bu[j][ni] = wb[(((split * 10 + 2 * kt + j) * 8 + n8b + ni) << 5) + lane];

        #pragma unroll
        for (int j = 0; j < 2; j++) {
            #pragma unroll
            for (int hh = 0; hh < 2; hh++) {
                const int k8l = 2 * j + hh;
                unsigned a[2][4];
                #pragma unroll
                for (int mi = 0; mi < 2; mi++) {
                    const unsigned* pp =
                        &As[(wm + mi * 16 + g) * G1_STRIDE + kt * 32 + k8l * 8 + t];
                    a[mi][0] = pp[0];
                    a[mi][1] = pp[8 * G1_STRIDE];
                    a[mi][2] = pp[4];
                    a[mi][3] = pp[8 * G1_STRIDE + 4];
                }
                #pragma unroll
                for (int mi = 0; mi < 2; mi++)
                    #pragma unroll
                    for (int ni = 0; ni < 4; ni++) {
                        unsigned b0 = hh ? bu[j][ni].z : bu[j][ni].x;
                        unsigned b1 = hh ? bu[j][ni].w : bu[j][ni].y;
                        mma_tf32(acc[mi][ni], a[mi][0], a[mi][1], a[mi][2], a[mi][3], b0, b1);
                    }
            }
        }
    }

    // ---- epilogue: stage to smem, write partials in A-fragment order ----
    __syncthreads();
    float* s = reinterpret_cast<float*>(As);   // [64][68] floats
    #pragma unroll
    for (int mi = 0; mi < 2; mi++)
        #pragma unroll
        for (int ni = 0; ni < 4; ni++) {
            int row = wm + mi * 16 + g;
            int col = wn + ni * 8 + 2 * t;
            *reinterpret_cast<float2*>(&s[row * 68 + col]) =
                make_float2(acc[mi][ni][0], acc[mi][ni][1]);
            *reinterpret_cast<float2*>(&s[(row + 8) * 68 + col]) =
                make_float2(acc[mi][ni][2], acc[mi][ni][3]);
        }
    __syncthreads();

    float4* dst = g_hp4 + (size_t)split * HQ_N + (size_t)(m0 >> 4) * 256;
    #pragma unroll
    for (int jj = 0; jj < 8; jj++) {
        int idx = tid + jj * 128;              // 0..1023 = ml*256 + k8*32 + lane
        int ln  = idx & 31;
        int k8  = (idx >> 5) & 7;
        int ml  = idx >> 8;
        int gg = ln >> 2, tt = ln & 3;
        const float* r0 = &s[(ml * 16 + gg) * 68 + k8 * 8 + tt];
        const float* r1 = r0 + 8 * 68;
        dst[idx] = make_float4(r0[0], r1[0], r0[4], r1[4]);
    }
}

// ---------------------------------------------------------------------------
// Reduce: g_hq = cvt_tf32( sum over splits of g_hp4 ). Elementwise, coalesced.
// ---------------------------------------------------------------------------
__global__ __launch_bounds__(256) void lora_reduce() {
    int i = blockIdx.x * 256 + threadIdx.x;    // < HQ_N (grid 512)
    float4 sv = g_hp4[i];
    #pragma unroll
    for (int sp = 1; sp < NSPLIT; sp++) {
        float4 v = g_hp4[(size_t)sp * HQ_N + i];
        sv.x += v.x; sv.y += v.y; sv.z += v.z; sv.w += v.w;
    }
    uint4 o;
    o.x = f2tf(sv.x); o.y = f2tf(sv.y); o.z = f2tf(sv.z); o.w = f2tf(sv.w);
    g_hq[i] = o;
}

// ---------------------------------------------------------------------------
// GEMM2: out[m,o] = h[m,:] @ W_up[b]^T, K=64.
//   CTA 64m x 64n, block 256 (8 warps as 2m x 4n, warp tile 32m x 16n).
//   acc = 16 floats/thread -> ~52 regs -> ~39 resident warps/SM (latency fix).
//   grid (128, 20) = 2560 CTAs. A/B fragments LDG from L2-hot packed scratch.
//   Staged-store epilogue: frags -> smem (stride 72, conflict-free) ->
//   coalesced STG.128.
// ---------------------------------------------------------------------------
__global__ __launch_bounds__(256) void lora_gemm2(float* __restrict__ out) {
    __shared__ float s[64 * 72];   // 18432 B

    const int tid   = threadIdx.x;
    const int m0    = blockIdx.x * 64;
    const int n0    = blockIdx.y * 64;
    const int batch = blockIdx.x >> 4;

    const int wid  = tid >> 5;
    const int lane = tid & 31;
    const int wm = (wid & 1) * 32;     // 0 / 32
    const int wn = (wid >> 1) * 16;    // 0,16,32,48
    const int g = lane >> 2;
    const int t = lane & 3;

    const uint4* __restrict__ Ab = g_hq + (size_t)((m0 + wm) >> 4) * 256 + lane;
    const uint4* __restrict__ Bb = g_wup
        + ((size_t)batch * 160 + ((n0 + wn) >> 3)) * 128 + lane;

    float acc[2][2][4];
    #pragma unroll
    for (int mi = 0; mi < 2; mi++)
        #pragma unroll
        for (int ni = 0; ni < 2; ni++)
            #pragma unroll
            for (int j = 0; j < 4; j++) acc[mi][ni][j] = 0.f;

    #pragma unroll
    for (int k16 = 0; k16 < 4; k16++) {
        uint4 alo[2], ahi[2], bu[2];
        #pragma unroll
        for (int mi = 0; mi < 2; mi++) {
            alo[mi] = Ab[mi * 256 + (2 * k16) * 32];
            ahi[mi] = Ab[mi * 256 + (2 * k16 + 1) * 32];
        }
        #pragma unroll
        for (int ni = 0; ni < 2; ni++)
            bu[ni] = Bb[ni * 128 + k16 * 32];

        #pragma unroll
        for (int mi = 0; mi < 2; mi++)
            #pragma unroll
            for (int ni = 0; ni < 2; ni++) {
                mma_tf32(acc[mi][ni], alo[mi].x, alo[mi].y, alo[mi].z, alo[mi].w,
                         bu[ni].x, bu[ni].y);
                mma_tf32(acc[mi][ni], ahi[mi].x, ahi[mi].y, ahi[mi].z, ahi[mi].w,
                         bu[ni].z, bu[ni].w);
            }
    }

    // ---- staged-store epilogue: stride-72 smem -> coalesced STG.128 ----
    #pragma unroll
    for (int mi = 0; mi < 2; mi++)
        #pragma unroll
        for (int ni = 0; ni < 2; ni++) {
            int row = wm + mi * 16 + g;
            int col = wn + ni * 8 + 2 * t;
            *reinterpret_cast<float2*>(&s[row * 72 + col]) =
                make_float2(acc[mi][ni][0], acc[mi][ni][1]);
            *reinterpret_cast<float2*>(&s[(row + 8) * 72 + col]) =
                make_float2(acc[mi][ni][2], acc[mi][ni][3]);
        }
    __syncthreads();

    #pragma unroll
    for (int j = 0; j < 4; j++) {
        int idx = tid + j * 256;               // 64 rows x 16 float4
        int row = idx >> 4;
        int seg = idx & 15;
        float4 v = *reinterpret_cast<const float4*>(&s[row * 72 + seg * 4]);
        *reinterpret_cast<float4*>(&out[(size_t)(m0 + row) * DOUT + n0 + seg * 4]) = v;
    }
}

// ---------------------------------------------------------------------------
extern "C" void kernel_launch(void* const* d_in, const int* in_sizes, int n_in,
                              void* d_out, int out_size) {
    const float* x     = (const float*)d_in[0];
    const float* embed = (const float*)d_in[1];
    if (n_in >= 2 && in_sizes[0] == NB * EMB_STRIDE) {
        x     = (const float*)d_in[1];
        embed = (const float*)d_in[0];
    }
    float* out = (float*)d_out;

    lora_prepack<<<(WDP_N + WUP_N) / 256, 256>>>(embed);
    lora_gemm1<<<dim3(128, NSPLIT), 128>>>(x);
    lora_reduce<<<HQ_N / 256, 256>>>();
    lora_gemm2<<<dim3(128, 20), 256>>>(out);
}